// round 2
// baseline (speedup 1.0000x reference)
#include <cuda_runtime.h>
#include <math.h>

#define B_ 16
#define C_ 64          // Cin = Cout
#define HW_ 64
#define E_ 16
#define KTOP_ 4
#define WPE_ (64*64*9) // weights per expert = 36864

typedef unsigned long long ull;

// ---------------- scratch (device globals; no allocations allowed) ----------
__device__ float g_gate_x[B_ * C_];          // (b, ci) means
__device__ float g_gates[B_ * E_];           // dense gates
__device__ float g_beff[B_ * C_];            // effective bias per (b, co)
__device__ float g_Weff[B_ * WPE_];          // effective weights per batch (9.4 MB)

__device__ __forceinline__ void fma2(ull& d, ull a, ull b) {
    asm("fma.rn.f32x2 %0, %1, %2, %0;" : "+l"(d) : "l"(a), "l"(b));
}

// ---------------- kernel 1: gate_x = mean over HxW -------------------------
__global__ __launch_bounds__(256) void mean_kernel(const float* __restrict__ x) {
    const int bc = blockIdx.x;                 // b*64 + ci  (1024 blocks)
    const float* p = x + (size_t)bc * (HW_ * HW_);
    float s = 0.f;
    for (int i = threadIdx.x; i < HW_ * HW_; i += 256) s += p[i];
    for (int o = 16; o > 0; o >>= 1) s += __shfl_xor_sync(0xffffffffu, s, o);
    __shared__ float red[8];
    if ((threadIdx.x & 31) == 0) red[threadIdx.x >> 5] = s;
    __syncthreads();
    if (threadIdx.x == 0) {
        float t = 0.f;
        #pragma unroll
        for (int w = 0; w < 8; w++) t += red[w];
        g_gate_x[bc] = t * (1.0f / (HW_ * HW_));
    }
}

// ---------------- kernel 2: gating + top-k + loss + beff --------------------
__global__ __launch_bounds__(256) void gate_kernel(const float* __restrict__ w_gate,
                                                   const float* __restrict__ bias,
                                                   float* __restrict__ loss_out) {
    __shared__ float logit[B_][E_];
    __shared__ float sg[B_][E_];
    const int tid = threadIdx.x;            // 256 = 16*16
    const int b = tid >> 4, e = tid & 15;

    float s = 0.f;
    #pragma unroll 8
    for (int ci = 0; ci < C_; ci++) s += g_gate_x[b * C_ + ci] * w_gate[ci * E_ + e];
    logit[b][e] = s;
    sg[b][e] = 0.f;
    __syncthreads();

    if (tid < B_) {
        const int bb = tid;
        float mx = -1e30f;
        #pragma unroll
        for (int j = 0; j < E_; j++) mx = fmaxf(mx, logit[bb][j]);
        float p[E_]; float sum = 0.f;
        #pragma unroll
        for (int j = 0; j < E_; j++) { p[j] = __expf(logit[bb][j] - mx); sum += p[j]; }
        const float inv = 1.0f / sum;
        #pragma unroll
        for (int j = 0; j < E_; j++) p[j] *= inv;
        bool used[E_] = {false};
        float tv[KTOP_]; int ti[KTOP_]; float tsum = 0.f;
        #pragma unroll
        for (int k = 0; k < KTOP_; k++) {
            float best = -1.f; int bi = 0;
            #pragma unroll
            for (int j = 0; j < E_; j++)
                if (!used[j] && p[j] > best) { best = p[j]; bi = j; }
            used[bi] = true; tv[k] = best; ti[k] = bi; tsum += best;
        }
        const float denom = 1.0f / (tsum + 1e-6f);
        #pragma unroll
        for (int k = 0; k < KTOP_; k++) sg[bb][ti[k]] = tv[k] * denom;
    }
    __syncthreads();

    g_gates[tid] = sg[b][e];

    if (tid == 0) {
        float mi = 0.f, ml = 0.f;
        float imp[E_], ld[E_];
        for (int j = 0; j < E_; j++) {
            float si = 0.f, sl = 0.f;
            for (int bb = 0; bb < B_; bb++) {
                float g = sg[bb][j];
                si += g;
                sl += (g > 0.f) ? 1.f : 0.f;
            }
            imp[j] = si; ld[j] = sl; mi += si; ml += sl;
        }
        mi *= (1.0f / E_); ml *= (1.0f / E_);
        float vi = 0.f, vl = 0.f;
        for (int j = 0; j < E_; j++) {
            float di = imp[j] - mi, dl = ld[j] - ml;
            vi += di * di; vl += dl * dl;
        }
        vi *= (1.0f / (E_ - 1)); vl *= (1.0f / (E_ - 1));
        float cvi = vi / (mi * mi + 1e-10f);
        float cvl = vl / (ml * ml + 1e-10f);
        loss_out[0] = (cvi + cvl) * 0.01f;
    }
    __syncthreads();

    for (int idx = tid; idx < B_ * C_; idx += 256) {
        const int bb = idx >> 6, co = idx & 63;
        float s2 = 0.f;
        #pragma unroll
        for (int ee = 0; ee < E_; ee++) s2 += sg[bb][ee] * bias[ee * C_ + co];
        g_beff[idx] = s2;
    }
}

// ---------------- kernel 3: Weff[b] = sum_e g[b,e] * W[e] -------------------
__global__ __launch_bounds__(256) void weff_kernel(const float* __restrict__ W) {
    const int b = blockIdx.y;
    const int i = blockIdx.x * 256 + threadIdx.x;    // < 36864
    if (i >= WPE_) return;
    float s = 0.f;
    #pragma unroll
    for (int e = 0; e < E_; e++) s += g_gates[b * E_ + e] * W[(size_t)e * WPE_ + i];
    g_Weff[(size_t)b * WPE_ + i] = s;
}

// ---------------- kernel 4: per-batch conv, ci-pair packed f32x2 ------------
// grid: (16 row-tiles of 4 rows, 4 co-tiles of 16 co, 16 batches); block 256.
// thread: co_l = tid>>4 in [0,16), cq = tid&15 -> output cols 4cq..4cq+3.
// smem x layout: [cp(8)][r(6)][physq(36)][4]  where a "quad" = 2 cols x (ci even, ci odd)
// quad swizzle: phys_q = q ^ ((q>>3)&3)  -> conflict-free LDS.128 across the warp.
#define XROW_ 144              // 36 quads * 4 floats per (cp, r) row
__global__ __launch_bounds__(256, 3) void conv_kernel(const float* __restrict__ x,
                                                      float* __restrict__ out) {
    const int b = blockIdx.z;
    const int co_base = blockIdx.y * 16;
    const int row_base = blockIdx.x * 4;
    const int tid = threadIdx.x;
    const int co_l = tid >> 4;
    const int cq = tid & 15;

    __shared__ float xs[8 * 6 * XROW_];     // 27648 B
    __shared__ float ws[16 * 9 * 16];       //  9216 B  [co][tap][ci16]

    // per-thread swizzled quad offsets (constant): quads 2cq, 2cq+1, 2cq+2
    int ph[3];
    #pragma unroll
    for (int d = 0; d < 3; d++) {
        int q = 2 * cq + d;
        ph[d] = (q ^ ((q >> 3) & 3)) * 4;
    }

    ull acc[4][4];
    #pragma unroll
    for (int r = 0; r < 4; r++)
        #pragma unroll
        for (int j = 0; j < 4; j++) acc[r][j] = 0ull;

    const float* xb = x + (size_t)b * C_ * HW_ * HW_;
    const float* wb = g_Weff + (size_t)b * WPE_;

    for (int cc = 0; cc < C_; cc += 16) {
        // ---- stage x chunk: 16 channels x (4 rows + halo) x (64 cols + halo) ----
        #pragma unroll 1
        for (int idx = tid; idx < 16 * 6 * 66; idx += 256) {
            const int ci = idx / 396;
            const int rem = idx - ci * 396;
            const int r = rem / 66;
            const int c = rem - r * 66;
            const int gr = row_base - 1 + r;
            const int gc = c - 1;
            float v = 0.f;
            if (gr >= 0 && gr < HW_ && gc >= 0 && gc < HW_)
                v = xb[((cc + ci) * HW_ + gr) * HW_ + gc];
            const int q = c >> 1;
            const int pq = q ^ ((q >> 3) & 3);
            xs[((ci >> 1) * 6 + r) * XROW_ + pq * 4 + (c & 1) * 2 + (ci & 1)] = v;
        }
        // ---- stage weights: [co][tap][ci] ----
        #pragma unroll 1
        for (int idx = tid; idx < 16 * 9 * 16; idx += 256) {
            const int ci = idx & 15;
            const int t = (idx >> 4) % 9;
            const int col = idx / 144;
            ws[(col * 9 + t) * 16 + ci] = wb[((co_base + col) * C_ + cc + ci) * 9 + t];
        }
        __syncthreads();

        #pragma unroll 1
        for (int cp = 0; cp < 8; cp++) {
            ull w2[9];
            #pragma unroll
            for (int t = 0; t < 9; t++)
                w2[t] = *(const ull*)&ws[(co_l * 9 + t) * 16 + 2 * cp];

            const float* xrow = &xs[(cp * 6) * XROW_];
            #pragma unroll
            for (int lr = 0; lr < 6; lr++) {
                ull x2[6];
                #pragma unroll
                for (int d = 0; d < 3; d++) {
                    ulonglong2 v = *(const ulonglong2*)(xrow + lr * XROW_ + ph[d]);
                    x2[2 * d] = v.x;
                    x2[2 * d + 1] = v.y;
                }
                #pragma unroll
                for (int dy = 0; dy < 3; dy++) {
                    const int ro = lr - dy;
                    if (ro >= 0 && ro < 4) {
                        #pragma unroll
                        for (int j = 0; j < 4; j++) {
                            fma2(acc[ro][j], w2[dy * 3 + 0], x2[j + 0]);
                            fma2(acc[ro][j], w2[dy * 3 + 1], x2[j + 1]);
                            fma2(acc[ro][j], w2[dy * 3 + 2], x2[j + 2]);
                        }
                    }
                }
            }
        }
        __syncthreads();
    }

    const int co = co_base + co_l;
    const float bias = g_beff[b * C_ + co];
    #pragma unroll
    for (int ro = 0; ro < 4; ro++) {
        float4 v;
        float2 p0 = *(float2*)&acc[ro][0];
        float2 p1 = *(float2*)&acc[ro][1];
        float2 p2 = *(float2*)&acc[ro][2];
        float2 p3 = *(float2*)&acc[ro][3];
        v.x = p0.x + p0.y + bias;
        v.y = p1.x + p1.y + bias;
        v.z = p2.x + p2.y + bias;
        v.w = p3.x + p3.y + bias;
        *(float4*)&out[(((size_t)b * C_ + co) * HW_ + row_base + ro) * HW_ + cq * 4] = v;
    }
}

// ---------------- launch --------------------------------------------------
extern "C" void kernel_launch(void* const* d_in, const int* in_sizes, int n_in,
                              void* d_out, int out_size) {
    const float* x      = (const float*)d_in[0];   // (16,64,64,64)
    const float* w_gate = (const float*)d_in[1];   // (64,16)
    const float* W      = (const float*)d_in[3];   // (16,64,64,3,3)
    const float* bias   = (const float*)d_in[4];   // (16,64)
    float* out = (float*)d_out;                    // y flat then loss

    mean_kernel<<<B_ * C_, 256>>>(x);
    gate_kernel<<<1, 256>>>(w_gate, bias, out + (out_size - 1));
    {
        dim3 g((WPE_ + 255) / 256, B_);
        weff_kernel<<<g, 256>>>(W);
    }
    {
        dim3 g(16, 4, B_);
        conv_kernel<<<g, 256>>>(x, out);
    }
}

// round 4
// speedup vs baseline: 2.2323x; 2.2323x over previous
#include <cuda_runtime.h>
#include <cuda_bf16.h>
#include <math.h>
#include <stdint.h>

#define B_ 16
#define C_ 64
#define HW_ 64
#define E_ 16
#define KTOP_ 4

// ------------------------- scratch (device globals) -------------------------
__device__ float g_gate_x[B_ * C_];
__device__ float g_gates[B_ * E_];
__device__ float g_beff[B_ * C_];
__device__ __nv_bfloat16 g_Whi[B_ * 9 * C_ * C_];   // [b][tap][co][ci]
__device__ __nv_bfloat16 g_Wlo[B_ * 9 * C_ * C_];
__device__ __nv_bfloat16 g_xT_hi[(size_t)B_ * 66 * 66 * C_];  // [b][rp][cp][ci]
__device__ __nv_bfloat16 g_xT_lo[(size_t)B_ * 66 * 66 * C_];

// ------------------------- helpers ------------------------------------------
__device__ __forceinline__ uint32_t smem_u32(const void* p) {
    uint32_t a;
    asm("{ .reg .u64 t; cvta.to.shared.u64 t, %1; cvt.u32.u64 %0, t; }" : "=r"(a) : "l"(p));
    return a;
}
__device__ __forceinline__ void ldsm_x4(uint32_t* r, uint32_t addr) {
    asm volatile("ldmatrix.sync.aligned.m8n8.x4.shared.b16 {%0,%1,%2,%3}, [%4];"
        : "=r"(r[0]), "=r"(r[1]), "=r"(r[2]), "=r"(r[3]) : "r"(addr));
}
__device__ __forceinline__ void ldsm_x2(uint32_t* r, uint32_t addr) {
    asm volatile("ldmatrix.sync.aligned.m8n8.x2.shared.b16 {%0,%1}, [%2];"
        : "=r"(r[0]), "=r"(r[1]) : "r"(addr));
}
__device__ __forceinline__ void mma16816(float* d, const uint32_t* a, const uint32_t* b) {
    asm volatile(
        "mma.sync.aligned.m16n8k16.row.col.f32.bf16.bf16.f32 "
        "{%0,%1,%2,%3}, {%4,%5,%6,%7}, {%8,%9}, {%0,%1,%2,%3};"
        : "+f"(d[0]), "+f"(d[1]), "+f"(d[2]), "+f"(d[3])
        : "r"(a[0]), "r"(a[1]), "r"(a[2]), "r"(a[3]), "r"(b[0]), "r"(b[1]));
}

// ---------------- kernel 1: gate_x mean ------------------------------------
__global__ __launch_bounds__(256) void mean_kernel(const float* __restrict__ x) {
    const int bc = blockIdx.x;
    const float* p = x + (size_t)bc * (HW_ * HW_);
    float s = 0.f;
    for (int i = threadIdx.x; i < HW_ * HW_; i += 256) s += p[i];
    for (int o = 16; o > 0; o >>= 1) s += __shfl_xor_sync(0xffffffffu, s, o);
    __shared__ float red[8];
    if ((threadIdx.x & 31) == 0) red[threadIdx.x >> 5] = s;
    __syncthreads();
    if (threadIdx.x == 0) {
        float t = 0.f;
        #pragma unroll
        for (int w = 0; w < 8; w++) t += red[w];
        g_gate_x[bc] = t * (1.0f / (HW_ * HW_));
    }
}

// ---------------- kernel 2: gating + loss + beff ----------------------------
__global__ __launch_bounds__(256) void gate_kernel(const float* __restrict__ w_gate,
                                                   const float* __restrict__ bias,
                                                   float* __restrict__ loss_out) {
    __shared__ float logit[B_][E_];
    __shared__ float sg[B_][E_];
    const int tid = threadIdx.x;
    const int b = tid >> 4, e = tid & 15;

    float s = 0.f;
    #pragma unroll 8
    for (int ci = 0; ci < C_; ci++) s += g_gate_x[b * C_ + ci] * w_gate[ci * E_ + e];
    logit[b][e] = s;
    sg[b][e] = 0.f;
    __syncthreads();

    if (tid < B_) {
        const int bb = tid;
        float mx = -1e30f;
        #pragma unroll
        for (int j = 0; j < E_; j++) mx = fmaxf(mx, logit[bb][j]);
        float p[E_]; float sum = 0.f;
        #pragma unroll
        for (int j = 0; j < E_; j++) { p[j] = __expf(logit[bb][j] - mx); sum += p[j]; }
        const float inv = 1.0f / sum;
        #pragma unroll
        for (int j = 0; j < E_; j++) p[j] *= inv;
        bool used[E_] = {false};
        float tv[KTOP_]; int ti[KTOP_]; float tsum = 0.f;
        #pragma unroll
        for (int k = 0; k < KTOP_; k++) {
            float best = -1.f; int bi = 0;
            #pragma unroll
            for (int j = 0; j < E_; j++)
                if (!used[j] && p[j] > best) { best = p[j]; bi = j; }
            used[bi] = true; tv[k] = best; ti[k] = bi; tsum += best;
        }
        const float denom = 1.0f / (tsum + 1e-6f);
        #pragma unroll
        for (int k = 0; k < KTOP_; k++) sg[bb][ti[k]] = tv[k] * denom;
    }
    __syncthreads();

    g_gates[tid] = sg[b][e];

    if (tid == 0) {
        float mi = 0.f, ml = 0.f, imp[E_], ld[E_];
        for (int j = 0; j < E_; j++) {
            float si = 0.f, sl = 0.f;
            for (int bb = 0; bb < B_; bb++) {
                float g = sg[bb][j];
                si += g; sl += (g > 0.f) ? 1.f : 0.f;
            }
            imp[j] = si; ld[j] = sl; mi += si; ml += sl;
        }
        mi *= (1.0f / E_); ml *= (1.0f / E_);
        float vi = 0.f, vl = 0.f;
        for (int j = 0; j < E_; j++) {
            float di = imp[j] - mi, dl = ld[j] - ml;
            vi += di * di; vl += dl * dl;
        }
        vi *= (1.0f / (E_ - 1)); vl *= (1.0f / (E_ - 1));
        loss_out[0] = (vi / (mi * mi + 1e-10f) + vl / (ml * ml + 1e-10f)) * 0.01f;
    }
    __syncthreads();

    for (int idx = tid; idx < B_ * C_; idx += 256) {
        const int bb = idx >> 6, co = idx & 63;
        float s2 = 0.f;
        #pragma unroll
        for (int ee = 0; ee < E_; ee++) s2 += sg[bb][ee] * bias[ee * C_ + co];
        g_beff[idx] = s2;
    }
}

// ---------------- kernel 3: Weff -> bf16 hi/lo [b][tap][co][ci] -------------
// one block per co; W read exactly once chip-wide.
__global__ __launch_bounds__(256) void weff_kernel(const float* __restrict__ W) {
    const int co = blockIdx.x;
    __shared__ float Wsh[E_ * 576];     // [e][ci*9+t]
    __shared__ float gsh[B_ * E_];
    const int tid = threadIdx.x;
    for (int i = tid; i < E_ * 576; i += 256)
        Wsh[i] = W[(size_t)(i / 576) * (C_ * 576) + (size_t)co * 576 + (i % 576)];
    for (int i = tid; i < B_ * E_; i += 256) gsh[i] = g_gates[i];
    __syncthreads();

    for (int i = tid; i < B_ * 576; i += 256) {
        const int b = i / 576, j = i - b * 576;
        const int ci = j / 9, t = j - ci * 9;
        float s = 0.f;
        #pragma unroll
        for (int e = 0; e < E_; e++) s += gsh[b * E_ + e] * Wsh[e * 576 + j];
        __nv_bfloat16 h = __float2bfloat16(s);
        float lo = s - __bfloat162float(h);
        const size_t o = (((size_t)b * 9 + t) * C_ + co) * C_ + ci;
        g_Whi[o] = h;
        g_Wlo[o] = __float2bfloat16(lo);
    }
}

// ---------------- kernel 4: x -> padded, transposed, bf16-split -------------
__global__ __launch_bounds__(256) void xconv_kernel(const float* __restrict__ x) {
    const int rp = blockIdx.x;   // 0..65
    const int b = blockIdx.y;
    __shared__ float xs[64][65];
    const int tid = threadIdx.x;
    const bool rowin = (rp >= 1 && rp <= 64);
    if (rowin) {
        for (int i = tid; i < 64 * 64; i += 256) {
            const int ci = i >> 6, col = i & 63;
            xs[col][ci] = x[(((size_t)b * C_ + ci) * HW_ + (rp - 1)) * HW_ + col];
        }
    }
    __syncthreads();
    for (int i = tid; i < 66 * 32; i += 256) {
        const int cp = i >> 5;
        const int cj = i & 31;
        float v0 = 0.f, v1 = 0.f;
        if (rowin && cp >= 1 && cp <= 64) {
            v0 = xs[cp - 1][2 * cj];
            v1 = xs[cp - 1][2 * cj + 1];
        }
        __nv_bfloat16 h0 = __float2bfloat16(v0);
        __nv_bfloat16 h1 = __float2bfloat16(v1);
        __nv_bfloat162 hv; hv.x = h0; hv.y = h1;
        __nv_bfloat162 lv;
        lv.x = __float2bfloat16(v0 - __bfloat162float(h0));
        lv.y = __float2bfloat16(v1 - __bfloat162float(h1));
        const size_t o = (((size_t)b * 66 + rp) * 66 + cp) * 32 + cj;
        ((__nv_bfloat162*)g_xT_hi)[o] = hv;
        ((__nv_bfloat162*)g_xT_lo)[o] = lv;
    }
}

// ---------------- kernel 5: HMMA conv ---------------------------------------
// grid (8 rowgroups, 16 b), 512 threads = 16 warps; warp = M64 x N32.
// smem: xs hi [0, 84480), xs lo [84480, 168960), Bs hi/lo [168960, 185344)
#define XS_HALF 84480
#define BS_OFF  168960
#define SM_TOT  (BS_OFF + 16384)
__global__ __launch_bounds__(512, 1) void conv_kernel(float* __restrict__ out) {
    extern __shared__ char smem[];
    const uint32_t sb = smem_u32(smem);
    const int tid = threadIdx.x;
    const int lane = tid & 31, wid = tid >> 5;
    const int b = blockIdx.y;
    const int r0 = blockIdx.x * 8;
    const int mt = wid >> 1;       // pixel-row within block (0..7); pixels mt*64..+63
    const int nt = wid & 1;        // co half: nt*32

    // ---- stage x once: 10 padded rows x 66 cols x 64 ci, hi+lo -------------
    {
        const uint4* xh = (const uint4*)(g_xT_hi + (size_t)b * 66 * 66 * 64);
        const uint4* xl = (const uint4*)(g_xT_lo + (size_t)b * 66 * 66 * 64);
        for (int u = tid; u < 10560; u += 512) {
            const int half = (u >= 5280);
            const int v = half ? u - 5280 : u;
            const int q = v >> 3, s = v & 7;
            const int lr = q / 66, cp = q - lr * 66;
            const uint4 val = (half ? xl : xh)[(((size_t)(r0 + lr)) * 66 + cp) * 8 + s];
            const uint32_t dst = (uint32_t)half * XS_HALF + (uint32_t)q * 128 +
                                 (((uint32_t)s * 16) ^ (((uint32_t)(q & 7)) << 4));
            *(uint4*)(smem + dst) = val;
        }
    }

    float acc[4][4][4];
    #pragma unroll
    for (int f = 0; f < 4; f++)
        #pragma unroll
        for (int g = 0; g < 4; g++)
            #pragma unroll
            for (int k = 0; k < 4; k++) acc[f][g][k] = 0.f;

    // per-lane addressing components
    const int pl = lane & 15;                         // A fragment row (pixel col)
    const uint32_t kbA = ((uint32_t)(lane >> 4)) << 4; // +16B for k+8 matrices (A)
    const int q0 = mt * 66 + pl;
    const int nB = nt * 32 + (lane & 7);              // B n for nf=0
    const uint32_t kbB = ((uint32_t)((lane >> 3) & 1)) << 4; // +16B matrix1 (B)
    const uint32_t bswz = ((uint32_t)(nB & 7)) << 4;

    for (int t = 0; t < 9; t++) {
        const int dy = t / 3, dx = t - 3 * (t / 3);
        // ---- stage B (hi+lo) ----
        {
            const uint4* wh = (const uint4*)(g_Whi + ((size_t)b * 9 + t) * 4096);
            const uint4* wl = (const uint4*)(g_Wlo + ((size_t)b * 9 + t) * 4096);
            for (int u = tid; u < 1024; u += 512) {
                const int half = u >> 9, v = u & 511;
                const int co = v >> 3, s = v & 7;
                const uint4 val = (half ? wl : wh)[v];
                const uint32_t dst = BS_OFF + (uint32_t)half * 8192 + (uint32_t)co * 128 +
                                     (((uint32_t)s * 16) ^ (((uint32_t)(co & 7)) << 4));
                *(uint4*)(smem + dst) = val;
            }
        }
        __syncthreads();

        const int qd = q0 + dy * 66 + dx;
        const uint32_t aswz = ((uint32_t)(qd & 7)) << 4;
        const uint32_t abase = sb + (uint32_t)qd * 128;
        const uint32_t bbase = sb + BS_OFF + (uint32_t)nB * 128;

        #pragma unroll
        for (int ks = 0; ks < 4; ks++) {
            const uint32_t kA = ((uint32_t)ks * 32 + kbA) ^ aswz;
            const uint32_t kB = ((uint32_t)ks * 32 + kbB) ^ bswz;
            uint32_t bh[4][2], bl[4][2];
            #pragma unroll
            for (int g = 0; g < 4; g++) {
                ldsm_x2(bh[g], bbase + (uint32_t)g * 1024 + kB);
                ldsm_x2(bl[g], bbase + 8192 + (uint32_t)g * 1024 + kB);
            }
            #pragma unroll
            for (int f = 0; f < 4; f++) {
                uint32_t a[4];
                ldsm_x4(a, abase + (uint32_t)f * 2048 + kA);
                #pragma unroll
                for (int g = 0; g < 4; g++) mma16816(acc[f][g], a, bh[g]); // hi*hi
                #pragma unroll
                for (int g = 0; g < 4; g++) mma16816(acc[f][g], a, bl[g]); // hi*lo
                ldsm_x4(a, abase + XS_HALF + (uint32_t)f * 2048 + kA);
                #pragma unroll
                for (int g = 0; g < 4; g++) mma16816(acc[f][g], a, bh[g]); // lo*hi
            }
        }
        __syncthreads();
    }

    // ---- epilogue: regs -> smem transpose -> coalesced gmem ----------------
    float bias[4][2];
    #pragma unroll
    for (int g = 0; g < 4; g++) {
        const int c0 = nt * 32 + g * 8 + 2 * (lane & 3);
        bias[g][0] = g_beff[b * C_ + c0];
        bias[g][1] = g_beff[b * C_ + c0 + 1];
    }
    float* so = (float*)smem;     // [512 pixels][66]
    #pragma unroll
    for (int f = 0; f < 4; f++) {
        const int p0 = mt * 64 + f * 16 + (lane >> 2);
        #pragma unroll
        for (int g = 0; g < 4; g++) {
            const int c0 = nt * 32 + g * 8 + 2 * (lane & 3);
            so[p0 * 66 + c0]           = acc[f][g][0] + bias[g][0];
            so[p0 * 66 + c0 + 1]       = acc[f][g][1] + bias[g][1];
            so[(p0 + 8) * 66 + c0]     = acc[f][g][2] + bias[g][0];
            so[(p0 + 8) * 66 + c0 + 1] = acc[f][g][3] + bias[g][1];
        }
    }
    __syncthreads();
    for (int u = tid; u < 8192; u += 512) {
        const int co = u >> 7;
        const int pj = (u & 127) << 2;
        float4 v;
        v.x = so[(pj + 0) * 66 + co];
        v.y = so[(pj + 1) * 66 + co];
        v.z = so[(pj + 2) * 66 + co];
        v.w = so[(pj + 3) * 66 + co];
        ((float4*)(out + (((size_t)b * C_ + co) * HW_ + r0) * HW_))[u & 127] = v;
    }
}

// ---------------- launch -----------------------------------------------------
extern "C" void kernel_launch(void* const* d_in, const int* in_sizes, int n_in,
                              void* d_out, int out_size) {
    const float* x      = (const float*)d_in[0];
    const float* w_gate = (const float*)d_in[1];
    const float* W      = (const float*)d_in[3];
    const float* bias   = (const float*)d_in[4];
    float* out = (float*)d_out;

    cudaFuncSetAttribute(conv_kernel, cudaFuncAttributeMaxDynamicSharedMemorySize, SM_TOT);

    mean_kernel<<<B_ * C_, 256>>>(x);
    gate_kernel<<<1, 256>>>(w_gate, bias, out + (out_size - 1));
    weff_kernel<<<C_, 256>>>(W);
    xconv_kernel<<<dim3(66, B_), 256>>>(x);
    conv_kernel<<<dim3(8, B_), 512, SM_TOT>>>(out);
}

// round 5
// speedup vs baseline: 2.7936x; 1.2515x over previous
#include <cuda_runtime.h>
#include <cuda_fp16.h>
#include <math.h>
#include <stdint.h>

#define B_ 16
#define C_ 64
#define HW_ 64
#define E_ 16
#define KTOP_ 4

// ------------------------- scratch (device globals) -------------------------
__device__ float g_rowsum[B_ * 64 * C_];            // [b][row][ci] per-row sums
__device__ float g_gates[B_ * E_];
__device__ float g_beff[B_ * C_];
__device__ __half g_Whi[B_ * 9 * C_ * C_];          // [b][tap][co][ci]
__device__ __half g_Wlo[B_ * 9 * C_ * C_];
__device__ __half g_xT[(size_t)B_ * 66 * 66 * C_];  // [b][rp][cp][ci], padded

// ------------------------- helpers ------------------------------------------
__device__ __forceinline__ uint32_t smem_u32(const void* p) {
    uint32_t a;
    asm("{ .reg .u64 t; cvta.to.shared.u64 t, %1; cvt.u32.u64 %0, t; }" : "=r"(a) : "l"(p));
    return a;
}
__device__ __forceinline__ void ldsm_x4(uint32_t* r, uint32_t addr) {
    asm volatile("ldmatrix.sync.aligned.m8n8.x4.shared.b16 {%0,%1,%2,%3}, [%4];"
        : "=r"(r[0]), "=r"(r[1]), "=r"(r[2]), "=r"(r[3]) : "r"(addr));
}
__device__ __forceinline__ void mma16816(float* d, const uint32_t* a, const uint32_t* b) {
    asm volatile(
        "mma.sync.aligned.m16n8k16.row.col.f32.f16.f16.f32 "
        "{%0,%1,%2,%3}, {%4,%5,%6,%7}, {%8,%9}, {%0,%1,%2,%3};"
        : "+f"(d[0]), "+f"(d[1]), "+f"(d[2]), "+f"(d[3])
        : "r"(a[0]), "r"(a[1]), "r"(a[2]), "r"(a[3]), "r"(b[0]), "r"(b[1]));
}
__device__ __forceinline__ void cp_async16(uint32_t dst, const void* src) {
    asm volatile("cp.async.cg.shared.global [%0], [%1], 16;" :: "r"(dst), "l"(src));
}
#define CP_COMMIT() asm volatile("cp.async.commit_group;" ::: "memory")
#define CP_WAIT0()  asm volatile("cp.async.wait_group 0;" ::: "memory")

// ---------------- kernel 1: x -> padded fp16 transpose + row sums -----------
__global__ __launch_bounds__(256) void xconv_kernel(const float* __restrict__ x) {
    const int rp = blockIdx.x;   // 0..65
    const int b = blockIdx.y;
    __shared__ float xs[64][65];
    const int tid = threadIdx.x;
    const bool rowin = (rp >= 1 && rp <= 64);
    if (rowin) {
        for (int i = tid; i < 64 * 64; i += 256) {
            const int ci = i >> 6, col = i & 63;
            xs[col][ci] = x[(((size_t)b * C_ + ci) * HW_ + (rp - 1)) * HW_ + col];
        }
    }
    __syncthreads();

    // per-row channel sums (deterministic partial for the gate mean)
    if (rowin && tid < 64) {
        float s = 0.f;
        #pragma unroll 8
        for (int col = 0; col < 64; col++) s += xs[col][tid];
        g_rowsum[(b * 64 + (rp - 1)) * C_ + tid] = s;
    }

    for (int i = tid; i < 66 * 32; i += 256) {
        const int cp = i >> 5;
        const int cj = i & 31;
        float v0 = 0.f, v1 = 0.f;
        if (rowin && cp >= 1 && cp <= 64) {
            v0 = xs[cp - 1][2 * cj];
            v1 = xs[cp - 1][2 * cj + 1];
        }
        __half2 hv;
        hv.x = __float2half_rn(v0);
        hv.y = __float2half_rn(v1);
        const size_t o = (((size_t)b * 66 + rp) * 66 + cp) * 32 + cj;
        ((__half2*)g_xT)[o] = hv;
    }
}

// ---------------- kernel 2: gating + loss + beff ----------------------------
__global__ __launch_bounds__(256) void gate_kernel(const float* __restrict__ w_gate,
                                                   const float* __restrict__ bias,
                                                   float* __restrict__ loss_out) {
    __shared__ float gx[B_ * C_];
    __shared__ float logit[B_][E_];
    __shared__ float sg[B_][E_];
    const int tid = threadIdx.x;
    const int b = tid >> 4, e = tid & 15;

    // finish the mean: reduce 64 row sums per (b, ci)
    for (int idx = tid; idx < B_ * C_; idx += 256) {
        const int bb = idx >> 6, ci = idx & 63;
        float s = 0.f;
        #pragma unroll 8
        for (int r = 0; r < 64; r++) s += g_rowsum[(bb * 64 + r) * C_ + ci];
        gx[idx] = s * (1.0f / (HW_ * HW_));
    }
    __syncthreads();

    float s = 0.f;
    #pragma unroll 8
    for (int ci = 0; ci < C_; ci++) s += gx[b * C_ + ci] * w_gate[ci * E_ + e];
    logit[b][e] = s;
    sg[b][e] = 0.f;
    __syncthreads();

    if (tid < B_) {
        const int bb = tid;
        float mx = -1e30f;
        #pragma unroll
        for (int j = 0; j < E_; j++) mx = fmaxf(mx, logit[bb][j]);
        float p[E_]; float sum = 0.f;
        #pragma unroll
        for (int j = 0; j < E_; j++) { p[j] = __expf(logit[bb][j] - mx); sum += p[j]; }
        const float inv = 1.0f / sum;
        #pragma unroll
        for (int j = 0; j < E_; j++) p[j] *= inv;
        bool used[E_] = {false};
        float tv[KTOP_]; int ti[KTOP_]; float tsum = 0.f;
        #pragma unroll
        for (int k = 0; k < KTOP_; k++) {
            float best = -1.f; int bi = 0;
            #pragma unroll
            for (int j = 0; j < E_; j++)
                if (!used[j] && p[j] > best) { best = p[j]; bi = j; }
            used[bi] = true; tv[k] = best; ti[k] = bi; tsum += best;
        }
        const float denom = 1.0f / (tsum + 1e-6f);
        #pragma unroll
        for (int k = 0; k < KTOP_; k++) sg[bb][ti[k]] = tv[k] * denom;
    }
    __syncthreads();

    g_gates[tid] = sg[b][e];

    if (tid == 0) {
        float mi = 0.f, ml = 0.f, imp[E_], ld[E_];
        for (int j = 0; j < E_; j++) {
            float si = 0.f, sl = 0.f;
            for (int bb = 0; bb < B_; bb++) {
                float g = sg[bb][j];
                si += g; sl += (g > 0.f) ? 1.f : 0.f;
            }
            imp[j] = si; ld[j] = sl; mi += si; ml += sl;
        }
        mi *= (1.0f / E_); ml *= (1.0f / E_);
        float vi = 0.f, vl = 0.f;
        for (int j = 0; j < E_; j++) {
            float di = imp[j] - mi, dl = ld[j] - ml;
            vi += di * di; vl += dl * dl;
        }
        vi *= (1.0f / (E_ - 1)); vl *= (1.0f / (E_ - 1));
        loss_out[0] = (vi / (mi * mi + 1e-10f) + vl / (ml * ml + 1e-10f)) * 0.01f;
    }
    __syncthreads();

    for (int idx = tid; idx < B_ * C_; idx += 256) {
        const int bb = idx >> 6, co = idx & 63;
        float s2 = 0.f;
        #pragma unroll
        for (int ee = 0; ee < E_; ee++) s2 += sg[bb][ee] * bias[ee * C_ + co];
        g_beff[idx] = s2;
    }
}

// ---------------- kernel 3: Weff -> fp16 hi/lo [b][tap][co][ci] -------------
__global__ __launch_bounds__(256) void weff_kernel(const float* __restrict__ W) {
    const int co = blockIdx.x;
    __shared__ float Wsh[E_ * 576];     // [e][ci*9+t]
    __shared__ float gsh[B_ * E_];
    const int tid = threadIdx.x;
    for (int i = tid; i < E_ * 576; i += 256)
        Wsh[i] = W[(size_t)(i / 576) * (C_ * 576) + (size_t)co * 576 + (i % 576)];
    for (int i = tid; i < B_ * E_; i += 256) gsh[i] = g_gates[i];
    __syncthreads();

    for (int i = tid; i < B_ * 576; i += 256) {
        const int b = i / 576, j = i - b * 576;
        const int ci = j / 9, t = j - ci * 9;
        float s = 0.f;
        #pragma unroll
        for (int e = 0; e < E_; e++) s += gsh[b * E_ + e] * Wsh[e * 576 + j];
        __half h = __float2half_rn(s);
        float lo = s - __half2float(h);
        const size_t o = (((size_t)b * 9 + t) * C_ + co) * C_ + ci;
        g_Whi[o] = h;
        g_Wlo[o] = __float2half_rn(lo);
    }
}

// ---------------- kernel 4: HMMA conv (2-pass fp16 split on W) --------------
// grid (8 rowgroups, 16 b), 512 threads = 16 warps; warp = M64 x N32.
// smem: xs [0, 84480) ; B double buffers [84480, 84480+2*16384)
// epilogue reuses smem from 0 as float[512][66].
#define XS_SZ   84480
#define BUF_SZ  16384
#define SM_TOT  135168
__global__ __launch_bounds__(512, 1) void conv_kernel(float* __restrict__ out) {
    extern __shared__ char smem[];
    const uint32_t sb = smem_u32(smem);
    const int tid = threadIdx.x;
    const int lane = tid & 31, wid = tid >> 5;
    const int b = blockIdx.y;
    const int r0 = blockIdx.x * 8;
    const int mt = wid >> 1;       // pixel-row group (0..7)
    const int nt = wid & 1;        // co half

    // ---- prologue: async-stage x (10 padded rows x 66 x 64ci fp16) ----------
    {
        const uint4* xh = (const uint4*)(g_xT + (size_t)b * 66 * 66 * 64);
        for (int u = tid; u < 5280; u += 512) {
            const int q = u >> 3, s = u & 7;
            const int lr = q / 66, cp = q - lr * 66;
            const uint32_t dst = sb + (uint32_t)q * 128 +
                                 (((uint32_t)s * 16) ^ (((uint32_t)(q & 7)) << 4));
            cp_async16(dst, xh + (((size_t)(r0 + lr)) * 66 + cp) * 8 + s);
        }
        CP_COMMIT();
    }
    // ---- stage B tap 0 into buffer 0 ----------------------------------------
    const uint4* whb = (const uint4*)(g_Whi + (size_t)b * 9 * 4096);
    const uint4* wlb = (const uint4*)(g_Wlo + (size_t)b * 9 * 4096);
    {
        for (int u = tid; u < 1024; u += 512) {
            const int half = u >> 9, v = u & 511;
            const int co = v >> 3, s = v & 7;
            const uint32_t dst = sb + XS_SZ + (uint32_t)half * 8192 + (uint32_t)co * 128 +
                                 (((uint32_t)s * 16) ^ (((uint32_t)(co & 7)) << 4));
            cp_async16(dst, (half ? wlb : whb) + v);
        }
        CP_COMMIT();
    }

    float acc[4][4][4];
    #pragma unroll
    for (int f = 0; f < 4; f++)
        #pragma unroll
        for (int g = 0; g < 4; g++)
            #pragma unroll
            for (int k = 0; k < 4; k++) acc[f][g][k] = 0.f;

    // per-lane addressing
    const int pl = lane & 15;
    const uint32_t kbA = ((uint32_t)(lane >> 4)) << 4;    // +16B for k8..15 (A)
    const int q0 = mt * 66 + pl;
    const int nB = nt * 32 + (lane & 7);
    const uint32_t kbB = ((uint32_t)((lane >> 3) & 1)) << 4;   // matrix within k16
    const uint32_t hB = ((uint32_t)(lane >> 4)) * 8192;        // lanes 16-31 -> lo array
    const uint32_t bswz = ((uint32_t)(nB & 7)) << 4;

    for (int t = 0; t < 9; t++) {
        CP_WAIT0();
        __syncthreads();

        // prefetch next tap's B into the other buffer
        if (t < 8) {
            const uint4* wh = whb + (t + 1) * 512;
            const uint4* wl = wlb + (t + 1) * 512;
            const uint32_t bufo = sb + XS_SZ + (uint32_t)(((t + 1) & 1)) * BUF_SZ;
            for (int u = tid; u < 1024; u += 512) {
                const int half = u >> 9, v = u & 511;
                const int co = v >> 3, s = v & 7;
                const uint32_t dst = bufo + (uint32_t)half * 8192 + (uint32_t)co * 128 +
                                     (((uint32_t)s * 16) ^ (((uint32_t)(co & 7)) << 4));
                cp_async16(dst, (half ? wl : wh) + v);
            }
            CP_COMMIT();
        }

        const int dy = t / 3, dx = t - 3 * (t / 3);
        const int qd = q0 + dy * 66 + dx;
        const uint32_t aswz = ((uint32_t)(qd & 7)) << 4;
        const uint32_t abase = sb + (uint32_t)qd * 128;
        const uint32_t bbase = sb + XS_SZ + (uint32_t)(t & 1) * BUF_SZ +
                               (uint32_t)nB * 128 + hB;

        #pragma unroll
        for (int ks = 0; ks < 4; ks++) {
            const uint32_t kA = ((uint32_t)ks * 32 + kbA) ^ aswz;
            const uint32_t kB = ((uint32_t)ks * 32 + kbB) ^ bswz;
            uint32_t bf[4][4];   // [g]: {bh0, bh1, bl0, bl1}
            #pragma unroll
            for (int g = 0; g < 4; g++)
                ldsm_x4(bf[g], bbase + (uint32_t)g * 1024 + kB);
            #pragma unroll
            for (int f = 0; f < 4; f++) {
                uint32_t a[4];
                ldsm_x4(a, abase + (uint32_t)f * 2048 + kA);
                #pragma unroll
                for (int g = 0; g < 4; g++) mma16816(acc[f][g], a, &bf[g][0]); // x*wh
                #pragma unroll
                for (int g = 0; g < 4; g++) mma16816(acc[f][g], a, &bf[g][2]); // x*wl
            }
        }
    }
    __syncthreads();

    // ---- epilogue: regs -> smem transpose -> coalesced gmem ----------------
    float bias[4][2];
    #pragma unroll
    for (int g = 0; g < 4; g++) {
        const int c0 = nt * 32 + g * 8 + 2 * (lane & 3);
        bias[g][0] = g_beff[b * C_ + c0];
        bias[g][1] = g_beff[b * C_ + c0 + 1];
    }
    float* so = (float*)smem;     // [512 pixels][66]
    #pragma unroll
    for (int f = 0; f < 4; f++) {
        const int p0 = mt * 64 + f * 16 + (lane >> 2);
        #pragma unroll
        for (int g = 0; g < 4; g++) {
            const int c0 = nt * 32 + g * 8 + 2 * (lane & 3);
            so[p0 * 66 + c0]           = acc[f][g][0] + bias[g][0];
            so[p0 * 66 + c0 + 1]       = acc[f][g][1] + bias[g][1];
            so[(p0 + 8) * 66 + c0]     = acc[f][g][2] + bias[g][0];
            so[(p0 + 8) * 66 + c0 + 1] = acc[f][g][3] + bias[g][1];
        }
    }
    __syncthreads();
    for (int u = tid; u < 8192; u += 512) {
        const int co = u >> 7;
        const int pj = (u & 127) << 2;
        float4 v;
        v.x = so[(pj + 0) * 66 + co];
        v.y = so[(pj + 1) * 66 + co];
        v.z = so[(pj + 2) * 66 + co];
        v.w = so[(pj + 3) * 66 + co];
        ((float4*)(out + (((size_t)b * C_ + co) * HW_ + r0) * HW_))[u & 127] = v;
    }
}

// ---------------- launch -----------------------------------------------------
extern "C" void kernel_launch(void* const* d_in, const int* in_sizes, int n_in,
                              void* d_out, int out_size) {
    const float* x      = (const float*)d_in[0];
    const float* w_gate = (const float*)d_in[1];
    const float* W      = (const float*)d_in[3];
    const float* bias   = (const float*)d_in[4];
    float* out = (float*)d_out;

    cudaFuncSetAttribute(conv_kernel, cudaFuncAttributeMaxDynamicSharedMemorySize, SM_TOT);

    xconv_kernel<<<dim3(66, B_), 256>>>(x);
    gate_kernel<<<1, 256>>>(w_gate, bias, out + (out_size - 1));
    weff_kernel<<<C_, 256>>>(W);
    conv_kernel<<<dim3(8, B_), 512, SM_TOT>>>(out);
}

// round 6
// speedup vs baseline: 3.7490x; 1.3420x over previous
#include <cuda_runtime.h>
#include <cuda_fp16.h>
#include <math.h>
#include <stdint.h>

#define B_ 16
#define C_ 64
#define HW_ 64
#define E_ 16
#define KTOP_ 4

// ------------------------- scratch (device globals) -------------------------
__device__ float g_rowsum[B_ * 64 * C_];            // [b][row][ci]
__device__ float g_beff[B_ * C_];
__device__ __half g_Whi[B_ * 9 * C_ * C_];          // [b][tap][co][ci]
__device__ __half g_xT[(size_t)B_ * 66 * 66 * C_];  // [b][rp][cp][ci]

// ------------------------- helpers ------------------------------------------
__device__ __forceinline__ uint32_t smem_u32(const void* p) {
    uint32_t a;
    asm("{ .reg .u64 t; cvta.to.shared.u64 t, %1; cvt.u32.u64 %0, t; }" : "=r"(a) : "l"(p));
    return a;
}
__device__ __forceinline__ void ldsm_x4(uint32_t* r, uint32_t addr) {
    asm volatile("ldmatrix.sync.aligned.m8n8.x4.shared.b16 {%0,%1,%2,%3}, [%4];"
        : "=r"(r[0]), "=r"(r[1]), "=r"(r[2]), "=r"(r[3]) : "r"(addr));
}
__device__ __forceinline__ void mma16816(float* d, const uint32_t* a, const uint32_t* b) {
    asm volatile(
        "mma.sync.aligned.m16n8k16.row.col.f32.f16.f16.f32 "
        "{%0,%1,%2,%3}, {%4,%5,%6,%7}, {%8,%9}, {%0,%1,%2,%3};"
        : "+f"(d[0]), "+f"(d[1]), "+f"(d[2]), "+f"(d[3])
        : "r"(a[0]), "r"(a[1]), "r"(a[2]), "r"(a[3]), "r"(b[0]), "r"(b[1]));
}
__device__ __forceinline__ void cp_async16(uint32_t dst, const void* src) {
    asm volatile("cp.async.cg.shared.global [%0], [%1], 16;" :: "r"(dst), "l"(src));
}
#define CP_COMMIT() asm volatile("cp.async.commit_group;" ::: "memory")
#define CP_WAIT0()  asm volatile("cp.async.wait_group 0;" ::: "memory")

// ---------------- kernel 1: x -> padded fp16 transpose + row sums -----------
__global__ __launch_bounds__(256) void xconv_kernel(const float* __restrict__ x) {
    const int rp = blockIdx.x;   // 0..65
    const int b = blockIdx.y;
    __shared__ float xs[64][65];
    const int tid = threadIdx.x;
    const bool rowin = (rp >= 1 && rp <= 64);
    if (rowin) {
        for (int i = tid; i < 64 * 64; i += 256) {
            const int ci = i >> 6, col = i & 63;
            xs[col][ci] = x[(((size_t)b * C_ + ci) * HW_ + (rp - 1)) * HW_ + col];
        }
    }
    __syncthreads();

    if (rowin && tid < 64) {
        float s = 0.f;
        #pragma unroll 8
        for (int col = 0; col < 64; col++) s += xs[col][tid];
        g_rowsum[(b * 64 + (rp - 1)) * C_ + tid] = s;
    }

    for (int i = tid; i < 66 * 32; i += 256) {
        const int cp = i >> 5;
        const int cj = i & 31;
        float v0 = 0.f, v1 = 0.f;
        if (rowin && cp >= 1 && cp <= 64) {
            v0 = xs[cp - 1][2 * cj];
            v1 = xs[cp - 1][2 * cj + 1];
        }
        __half2 hv;
        hv.x = __float2half_rn(v0);
        hv.y = __float2half_rn(v1);
        const size_t o = (((size_t)b * 66 + rp) * 66 + cp) * 32 + cj;
        ((__half2*)g_xT)[o] = hv;
    }
}

// ---------------- kernel 2: fused gating + loss + beff + Weff ---------------
// 64 blocks (one per co); every block recomputes the (tiny) gate identically.
__global__ __launch_bounds__(256) void gateweff_kernel(const float* __restrict__ w_gate,
                                                       const float* __restrict__ bias,
                                                       const float* __restrict__ W,
                                                       float* __restrict__ loss_out) {
    const int co = blockIdx.x;
    __shared__ float gx[B_ * C_];
    __shared__ float logit[B_][E_];
    __shared__ float sg[B_][E_];
    __shared__ float Wsh[E_ * 576];
    const int tid = threadIdx.x;
    const int b = tid >> 4, e = tid & 15;

    // stage this co's expert weights early (independent of gating)
    for (int i = tid; i < E_ * 576; i += 256)
        Wsh[i] = W[(size_t)(i / 576) * (C_ * 576) + (size_t)co * 576 + (i % 576)];

    // finish mean: reduce 64 row sums per (b, ci)
    for (int idx = tid; idx < B_ * C_; idx += 256) {
        const int bb = idx >> 6, ci = idx & 63;
        float s = 0.f;
        #pragma unroll 8
        for (int r = 0; r < 64; r++) s += g_rowsum[(bb * 64 + r) * C_ + ci];
        gx[idx] = s * (1.0f / (HW_ * HW_));
    }
    __syncthreads();

    float s = 0.f;
    #pragma unroll 8
    for (int ci = 0; ci < C_; ci++) s += gx[b * C_ + ci] * w_gate[ci * E_ + e];
    logit[b][e] = s;
    sg[b][e] = 0.f;
    __syncthreads();

    if (tid < B_) {
        const int bb = tid;
        float mx = -1e30f;
        #pragma unroll
        for (int j = 0; j < E_; j++) mx = fmaxf(mx, logit[bb][j]);
        float p[E_]; float sum = 0.f;
        #pragma unroll
        for (int j = 0; j < E_; j++) { p[j] = __expf(logit[bb][j] - mx); sum += p[j]; }
        const float inv = 1.0f / sum;
        #pragma unroll
        for (int j = 0; j < E_; j++) p[j] *= inv;
        bool used[E_] = {false};
        float tv[KTOP_]; int ti[KTOP_]; float tsum = 0.f;
        #pragma unroll
        for (int k = 0; k < KTOP_; k++) {
            float best = -1.f; int bi = 0;
            #pragma unroll
            for (int j = 0; j < E_; j++)
                if (!used[j] && p[j] > best) { best = p[j]; bi = j; }
            used[bi] = true; tv[k] = best; ti[k] = bi; tsum += best;
        }
        const float denom = 1.0f / (tsum + 1e-6f);
        #pragma unroll
        for (int k = 0; k < KTOP_; k++) sg[bb][ti[k]] = tv[k] * denom;
    }
    __syncthreads();

    // per-co effective bias (each block handles its own co)
    if (tid < B_) {
        float s2 = 0.f;
        #pragma unroll
        for (int ee = 0; ee < E_; ee++) s2 += sg[tid][ee] * bias[ee * C_ + co];
        g_beff[tid * C_ + co] = s2;
    }

    // loss (block 0 only)
    if (co == 0 && tid == 0) {
        float mi = 0.f, ml = 0.f, imp[E_], ld[E_];
        for (int j = 0; j < E_; j++) {
            float si = 0.f, sl = 0.f;
            for (int bb = 0; bb < B_; bb++) {
                float g = sg[bb][j];
                si += g; sl += (g > 0.f) ? 1.f : 0.f;
            }
            imp[j] = si; ld[j] = sl; mi += si; ml += sl;
        }
        mi *= (1.0f / E_); ml *= (1.0f / E_);
        float vi = 0.f, vl = 0.f;
        for (int j = 0; j < E_; j++) {
            float di = imp[j] - mi, dl = ld[j] - ml;
            vi += di * di; vl += dl * dl;
        }
        vi *= (1.0f / (E_ - 1)); vl *= (1.0f / (E_ - 1));
        loss_out[0] = (vi / (mi * mi + 1e-10f) + vl / (ml * ml + 1e-10f)) * 0.01f;
    }

    // Weff for this co: [b][tap][co][ci] fp16
    for (int i = tid; i < B_ * 576; i += 256) {
        const int bb = i / 576, j = i - bb * 576;
        const int ci = j / 9, t = j - ci * 9;
        float s2 = 0.f;
        #pragma unroll
        for (int ee = 0; ee < E_; ee++) s2 += sg[bb][ee] * Wsh[ee * 576 + j];
        g_Whi[(((size_t)bb * 9 + t) * C_ + co) * C_ + ci] = __float2half_rn(s2);
    }
}

// ---------------- kernel 3: HMMA conv (1-pass fp16) -------------------------
// grid (8 rowgroups, 16 b), 512 threads = 16 warps; warp = M64 x N32.
// smem: xs [0, 84480) ; all 9 B taps [84480, 84480+9*8192)
// epilogue reuses smem from 0 as float[512][66] (135168 B).
#define XS_SZ   84480
#define SM_TOT  (84480 + 9 * 8192)     // 158208
__global__ __launch_bounds__(512, 1) void conv_kernel(float* __restrict__ out) {
    extern __shared__ char smem[];
    const uint32_t sb = smem_u32(smem);
    const int tid = threadIdx.x;
    const int lane = tid & 31, wid = tid >> 5;
    const int b = blockIdx.y;
    const int r0 = blockIdx.x * 8;
    const int mt = wid >> 1;       // pixel-row group (0..7)
    const int nt = wid & 1;        // co half

    // ---- prologue: async-stage x (10 rows x 66 x 64ci) + all 9 B taps ------
    {
        const uint4* xh = (const uint4*)(g_xT + (size_t)b * 66 * 66 * 64);
        for (int u = tid; u < 5280; u += 512) {
            const int q = u >> 3, s = u & 7;
            const int lr = q / 66, cp = q - lr * 66;
            const uint32_t dst = sb + (uint32_t)q * 128 +
                                 (((uint32_t)s * 16) ^ (((uint32_t)(q & 7)) << 4));
            cp_async16(dst, xh + (((size_t)(r0 + lr)) * 66 + cp) * 8 + s);
        }
        const uint4* whb = (const uint4*)(g_Whi + (size_t)b * 9 * 4096);
        for (int u = tid; u < 4608; u += 512) {
            const int tap = u >> 9, v = u & 511;
            const int co = v >> 3, s = v & 7;
            const uint32_t dst = sb + XS_SZ + (uint32_t)tap * 8192 + (uint32_t)co * 128 +
                                 (((uint32_t)s * 16) ^ (((uint32_t)(co & 7)) << 4));
            cp_async16(dst, whb + u);
        }
        CP_COMMIT();
        CP_WAIT0();
        __syncthreads();
    }

    float acc[4][4][4];
    #pragma unroll
    for (int f = 0; f < 4; f++)
        #pragma unroll
        for (int g = 0; g < 4; g++)
            #pragma unroll
            for (int k = 0; k < 4; k++) acc[f][g][k] = 0.f;

    // per-lane addressing
    const int pl = lane & 15;
    const uint32_t kbA = ((uint32_t)(lane >> 4)) << 4;          // k8..15 matrices (A)
    const int q0 = mt * 66 + pl;
    const int rowB = nt * 32 + ((lane >> 4) << 3) + (lane & 7); // n row for B x4
    const uint32_t kbB = ((uint32_t)((lane >> 3) & 1)) << 4;    // k half (B)
    const uint32_t bswz = ((uint32_t)(lane & 7)) << 4;

    #pragma unroll
    for (int t = 0; t < 9; t++) {
        const int dy = t / 3, dx = t - 3 * (t / 3);
        const int qd = q0 + dy * 66 + dx;
        const uint32_t aswz = ((uint32_t)(qd & 7)) << 4;
        const uint32_t abase = sb + (uint32_t)qd * 128;
        const uint32_t bbase = sb + XS_SZ + (uint32_t)t * 8192 + (uint32_t)rowB * 128;

        #pragma unroll
        for (int ks = 0; ks < 4; ks++) {
            const uint32_t kA = ((uint32_t)ks * 32 + kbA) ^ aswz;
            const uint32_t kB = ((uint32_t)ks * 32 + kbB) ^ bswz;
            uint32_t bf[2][4];           // [pair]: {g0 k0, g0 k1, g1 k0, g1 k1}
            ldsm_x4(bf[0], bbase + kB);
            ldsm_x4(bf[1], bbase + 2048 + kB);
            #pragma unroll
            for (int f = 0; f < 4; f++) {
                uint32_t a[4];
                ldsm_x4(a, abase + (uint32_t)f * 2048 + kA);
                mma16816(acc[f][0], a, &bf[0][0]);
                mma16816(acc[f][1], a, &bf[0][2]);
                mma16816(acc[f][2], a, &bf[1][0]);
                mma16816(acc[f][3], a, &bf[1][2]);
            }
        }
    }
    __syncthreads();

    // ---- epilogue: regs -> smem transpose -> coalesced gmem ----------------
    float bias[4][2];
    #pragma unroll
    for (int g = 0; g < 4; g++) {
        const int c0 = nt * 32 + g * 8 + 2 * (lane & 3);
        bias[g][0] = g_beff[b * C_ + c0];
        bias[g][1] = g_beff[b * C_ + c0 + 1];
    }
    float* so = (float*)smem;     // [512 pixels][66]
    #pragma unroll
    for (int f = 0; f < 4; f++) {
        const int p0 = mt * 64 + f * 16 + (lane >> 2);
        #pragma unroll
        for (int g = 0; g < 4; g++) {
            const int c0 = nt * 32 + g * 8 + 2 * (lane & 3);
            so[p0 * 66 + c0]           = acc[f][g][0] + bias[g][0];
            so[p0 * 66 + c0 + 1]       = acc[f][g][1] + bias[g][1];
            so[(p0 + 8) * 66 + c0]     = acc[f][g][2] + bias[g][0];
            so[(p0 + 8) * 66 + c0 + 1] = acc[f][g][3] + bias[g][1];
        }
    }
    __syncthreads();
    for (int u = tid; u < 8192; u += 512) {
        const int co = u >> 7;
        const int pj = (u & 127) << 2;
        float4 v;
        v.x = so[(pj + 0) * 66 + co];
        v.y = so[(pj + 1) * 66 + co];
        v.z = so[(pj + 2) * 66 + co];
        v.w = so[(pj + 3) * 66 + co];
        ((float4*)(out + (((size_t)b * C_ + co) * HW_ + r0) * HW_))[u & 127] = v;
    }
}

// ---------------- launch -----------------------------------------------------
extern "C" void kernel_launch(void* const* d_in, const int* in_sizes, int n_in,
                              void* d_out, int out_size) {
    const float* x      = (const float*)d_in[0];
    const float* w_gate = (const float*)d_in[1];
    const float* W      = (const float*)d_in[3];
    const float* bias   = (const float*)d_in[4];
    float* out = (float*)d_out;

    cudaFuncSetAttribute(conv_kernel, cudaFuncAttributeMaxDynamicSharedMemorySize, SM_TOT);

    xconv_kernel<<<dim3(66, B_), 256>>>(x);
    gateweff_kernel<<<C_, 256>>>(w_gate, bias, W, out + (out_size - 1));
    conv_kernel<<<dim3(8, B_), 512, SM_TOT>>>(out);
}